// round 14
// baseline (speedup 1.0000x reference)
#include <cuda_runtime.h>
#include <cuda_bf16.h>
#include <cstdint>
#include <cstddef>

// ---------------- problem constants ----------------
#define D      512
#define D4     128
#define MAXN   50000
#define NG     2048
#define NLAYER 5

// ---------------- scratch (device globals; no allocation allowed) ----------
__device__ float g_h[(size_t)MAXN * D];        // node features fp32
__device__ float g_agg[(size_t)MAXN * D];      // aggregated messages fp32
__device__ float g_t[(size_t)MAXN * 2 * D];    // MLP hidden fp32 [N,1024]
__device__ float g_pooled[(size_t)NG * D];
__device__ float g_cnt[NG];

// split-bf16 transposed weights  Wt[n][k]
__device__ __nv_bfloat16 g_w1h[(size_t)NLAYER * 1024 * 512];
__device__ __nv_bfloat16 g_w1l[(size_t)NLAYER * 1024 * 512];
__device__ __nv_bfloat16 g_w2h[(size_t)NLAYER * 512 * 1024];
__device__ __nv_bfloat16 g_w2l[(size_t)NLAYER * 512 * 1024];
__device__ __nv_bfloat16 g_q1h[512 * 512];
__device__ __nv_bfloat16 g_q1l[512 * 512];
__device__ __nv_bfloat16 g_q2h[512 * 512];
__device__ __nv_bfloat16 g_q2l[512 * 512];

// ---------------- PTX helpers (baseline ISA only: sm_80+) ----------------
__device__ __forceinline__ uint32_t smem_u32(const void* p) {
    uint32_t a;
    asm("{ .reg .u64 t; cvta.to.shared.u64 t, %1; cvt.u32.u64 %0, t; }" : "=r"(a) : "l"(p));
    return a;
}

__device__ __forceinline__ void cp_async16(uint32_t dst, const void* src, bool pred) {
    int sz = pred ? 16 : 0;
    asm volatile("cp.async.cg.shared.global [%0], [%1], 16, %2;" :: "r"(dst), "l"(src), "r"(sz));
}

__device__ __forceinline__ void ldsm_x2(uint32_t* r, uint32_t addr) {
    asm volatile("ldmatrix.sync.aligned.m8n8.x2.shared.b16 {%0,%1}, [%2];"
                 : "=r"(r[0]), "=r"(r[1]) : "r"(addr));
}

__device__ __forceinline__ void mma16816(float* c, const uint32_t* a, const uint32_t* b) {
    asm volatile("mma.sync.aligned.m16n8k16.row.col.f32.bf16.bf16.f32 "
                 "{%0,%1,%2,%3}, {%4,%5,%6,%7}, {%8,%9}, {%0,%1,%2,%3};"
                 : "+f"(c[0]), "+f"(c[1]), "+f"(c[2]), "+f"(c[3])
                 : "r"(a[0]), "r"(a[1]), "r"(a[2]), "r"(a[3]), "r"(b[0]), "r"(b[1]));
}

// split a float2 into packed bf16x2 hi + residual lo
__device__ __forceinline__ void split2(float2 f, uint32_t& h, uint32_t& l) {
    __nv_bfloat162 hb = __floats2bfloat162_rn(f.x, f.y);
    float r0 = f.x - __bfloat162float(hb.x);
    float r1 = f.y - __bfloat162float(hb.y);
    __nv_bfloat162 lb = __floats2bfloat162_rn(r0, r1);
    h = *reinterpret_cast<uint32_t*>(&hb);
    l = *reinterpret_cast<uint32_t*>(&lb);
}

__device__ __forceinline__ void red_add_v2(float* addr, float a, float b) {
    asm volatile("red.global.add.v2.f32 [%0], {%1,%2};"
                 :: "l"(addr), "f"(a), "f"(b) : "memory");
}

// ---------------- smem layout (dynamic) ----------------
// per k16 stage: A fp32 [128][24] (96B rows, conflict-free) then
//                B bf16 [128][40] ([hi16|lo16|pad8] = 80B rows, ldmatrix conflict-free)
static constexpr int A_STRIDE_F = 24;
static constexpr int A_CHUNK    = 128 * A_STRIDE_F * 4;   // 12288 B
static constexpr int B_STRIDE_H = 40;
static constexpr int B_CHUNK    = 128 * B_STRIDE_H * 2;   // 10240 B
static constexpr int STAGE_SZ   = A_CHUNK + B_CHUNK;      // 22528 B
static constexpr int NSTAGE     = 4;
static constexpr int GEMM_SMEM  = NSTAGE * STAGE_SZ;      // 90112 B

// ---------------- split-bf16 warp-MMA GEMM, fp32 A (R8 config) ------------
// C[M,Ncols] = act(A[M,K] @ Wt[Ncols,K]^T + bias); Ncols%128==0, K%16==0.
// 8 warps as 2(row)x4(col); warp tile 64x32.
// Single __syncthreads per k-chunk; 4-stage cp.async pipeline.
// Optional fused outputs:
//   Agg != null : also write Agg[row][col] = v + se1[col] + se2[col]
//   Pool != null: also red.add v into Pool[batch[row]*Ncols + col]
__global__ __launch_bounds__(256)
void gemm_mma(const float* __restrict__ A,
              const __nv_bfloat16* __restrict__ Bhi, const __nv_bfloat16* __restrict__ Blo,
              const float* __restrict__ bias, float* __restrict__ Cf,
              int M, int Ncols, int K, int relu,
              float* __restrict__ Agg, const float* __restrict__ se1, const float* __restrict__ se2,
              float* __restrict__ Pool, const int* __restrict__ batch) {
    extern __shared__ char smem[];
    const int tid = threadIdx.x;
    const int lane = tid & 31;
    const int wid = tid >> 5;
    const int wm = wid & 1;          // 2 warp-rows  -> 64 rows each
    const int wn = wid >> 1;         // 4 warp-cols  -> 32 cols each
    const int r0 = blockIdx.y * 128;
    const int c0 = blockIdx.x * 128;

    float acc[4][4][4];
#pragma unroll
    for (int i = 0; i < 4; i++)
#pragma unroll
        for (int j = 0; j < 4; j++)
#pragma unroll
            for (int e = 0; e < 4; e++) acc[i][j][e] = 0.f;

    const int nk = K >> 4;

    auto load_stage = [&](int c, int s) {
        const int k0 = c << 4;
        char* st = smem + s * STAGE_SZ;
        // A fp32: 512 x 16B chunks (row 0..127, 4 chunks of 4 floats)
#pragma unroll
        for (int it = 0; it < 2; it++) {
            int id = tid + it * 256;
            int row = id >> 2, ch = id & 3;
            const float* src = A + (size_t)(r0 + row) * K + k0 + ch * 4;
            uint32_t dst = smem_u32(st + row * (A_STRIDE_F * 4) + ch * 16);
            cp_async16(dst, src, (r0 + row) < M);
        }
        // B bf16 hi/lo: 512 x 16B chunks
#pragma unroll
        for (int it = 0; it < 2; it++) {
            int id = tid + it * 256;
            int row = id >> 2, ch = id & 3;
            const __nv_bfloat16* src = (ch < 2 ? Bhi : Blo) + (size_t)(c0 + row) * K + k0 + (ch & 1) * 8;
            uint32_t dst = smem_u32(st + A_CHUNK + row * (B_STRIDE_H * 2) + ch * 16);
            cp_async16(dst, src, true);
        }
        asm volatile("cp.async.commit_group;" ::: "memory");
    };

    load_stage(0, 0);
    if (nk > 1) load_stage(1, 1);
    if (nk > 2) load_stage(2, 2);

    const int g = lane >> 2, tig = lane & 3;

    for (int c = 0; c < nk; c++) {
        const int s = c & 3;
        // wait until stage c's group is complete: allow min(2, nk-1-c) newer groups
        const int rem = nk - 1 - c;
        if (rem >= 2)      asm volatile("cp.async.wait_group 2;" ::: "memory");
        else if (rem == 1) asm volatile("cp.async.wait_group 1;" ::: "memory");
        else               asm volatile("cp.async.wait_group 0;" ::: "memory");
        __syncthreads();   // stage c visible to all; all warps done with stage (c-1)

        if (c + 3 < nk) load_stage(c + 3, (c + 3) & 3);   // writes stage (c-1)&3: now free

        const float* sA = reinterpret_cast<const float*>(smem + s * STAGE_SZ);
        char* sBbase = smem + s * STAGE_SZ + A_CHUNK;

        // A fragments: load fp32, split to hi/lo bf16 in registers
        uint32_t ah[4][4], al[4][4];
#pragma unroll
        for (int mi = 0; mi < 4; mi++) {
            const int ra = wm * 64 + mi * 16 + g;
            float2 f0 = *reinterpret_cast<const float2*>(sA + ra * A_STRIDE_F + tig * 2);
            float2 f1 = *reinterpret_cast<const float2*>(sA + (ra + 8) * A_STRIDE_F + tig * 2);
            float2 f2 = *reinterpret_cast<const float2*>(sA + ra * A_STRIDE_F + tig * 2 + 8);
            float2 f3 = *reinterpret_cast<const float2*>(sA + (ra + 8) * A_STRIDE_F + tig * 2 + 8);
            split2(f0, ah[mi][0], al[mi][0]);
            split2(f1, ah[mi][1], al[mi][1]);
            split2(f2, ah[mi][2], al[mi][2]);
            split2(f3, ah[mi][3], al[mi][3]);
        }
        // B fragments via ldmatrix
        uint32_t bh[4][2], bl[4][2];
#pragma unroll
        for (int ni = 0; ni < 4; ni++) {
            uint32_t bd = smem_u32(sBbase + (wn * 32 + ni * 8 + (lane & 7)) * (B_STRIDE_H * 2)
                                   + ((lane >> 3) & 1) * 16);
            ldsm_x2(bh[ni], bd);
            ldsm_x2(bl[ni], bd + 32);
        }
#pragma unroll
        for (int mi = 0; mi < 4; mi++)
#pragma unroll
            for (int ni = 0; ni < 4; ni++) {
                mma16816(acc[mi][ni], ah[mi], bh[ni]);
                mma16816(acc[mi][ni], ah[mi], bl[ni]);
                mma16816(acc[mi][ni], al[mi], bh[ni]);
            }
    }

    // ---- epilogue: bias + act + fp32 store (+ fused agg-init / pool) ----
#pragma unroll
    for (int mi = 0; mi < 4; mi++) {
#pragma unroll
        for (int ni = 0; ni < 4; ni++) {
            const int col = c0 + wn * 32 + ni * 8 + tig * 2;
            const float b0 = __ldg(bias + col), b1 = __ldg(bias + col + 1);
#pragma unroll
            for (int h = 0; h < 2; h++) {
                const int row = r0 + wm * 64 + mi * 16 + g + h * 8;
                if (row < M) {
                    float v0 = acc[mi][ni][h * 2 + 0] + b0;
                    float v1 = acc[mi][ni][h * 2 + 1] + b1;
                    if (relu) { v0 = fmaxf(v0, 0.f); v1 = fmaxf(v1, 0.f); }
                    *reinterpret_cast<float2*>(Cf + (size_t)row * Ncols + col) = make_float2(v0, v1);
                    if (Agg) {
                        float s0 = __ldg(se1 + col) + __ldg(se2 + col);
                        float s1 = __ldg(se1 + col + 1) + __ldg(se2 + col + 1);
                        *reinterpret_cast<float2*>(Agg + (size_t)row * Ncols + col) =
                            make_float2(v0 + s0, v1 + s1);
                    }
                    if (Pool) {
                        int gi = __ldg(batch + row);
                        red_add_v2(Pool + (size_t)gi * Ncols + col, v0, v1);
                    }
                }
            }
        }
    }
}

// ---------------- elementwise / graph kernels ----------------
__device__ __forceinline__ float4 f4add(float4 a, float4 b) {
    return make_float4(a.x + b.x, a.y + b.y, a.z + b.z, a.w + b.w);
}
__device__ __forceinline__ void red_add_v4(float* addr, float4 v) {
    asm volatile("red.global.add.v4.f32 [%0], {%1,%2,%3,%4};"
                 :: "l"(addr), "f"(v.x), "f"(v.y), "f"(v.z), "f"(v.w) : "memory");
}

// h = emb lookup; agg = h + selfloop emb (layer 0) fused
__global__ void atom_encode(const int* __restrict__ x, const float* __restrict__ ae1,
                            const float* __restrict__ ae2,
                            const float* __restrict__ be1l0, const float* __restrict__ be2l0,
                            int N) {
    int i = blockIdx.x * blockDim.x + threadIdx.x;
    if (i >= N * D4) return;
    int n = i >> 7, c = i & (D4 - 1);
    float4 v1 = reinterpret_cast<const float4*>(ae1)[x[2 * n] * D4 + c];
    float4 v2 = reinterpret_cast<const float4*>(ae2)[x[2 * n + 1] * D4 + c];
    float4 h = f4add(v1, v2);
    reinterpret_cast<float4*>(g_h)[i] = h;
    float4 e1 = reinterpret_cast<const float4*>(be1l0)[6 * D4 + c];
    float4 e2 = reinterpret_cast<const float4*>(be2l0)[3 * D4 + c];
    reinterpret_cast<float4*>(g_agg)[i] = f4add(h, f4add(e1, e2));
}

__global__ void edge_scatter(const int* __restrict__ src, const int* __restrict__ dst,
                             const int* __restrict__ ea, const float* __restrict__ be1l,
                             const float* __restrict__ be2l, int E) {
    int e = blockIdx.x * 2 + (threadIdx.x >> 7);
    if (e >= E) return;
    int c = threadIdx.x & 127;
    int s = src[e], d = dst[e];
    float4 m = reinterpret_cast<const float4*>(g_h)[s * D4 + c];
    float4 e1 = reinterpret_cast<const float4*>(be1l)[ea[2 * e] * D4 + c];
    float4 e2 = reinterpret_cast<const float4*>(be2l)[ea[2 * e + 1] * D4 + c];
    red_add_v4(&g_agg[(size_t)d * D + c * 4], f4add(m, f4add(e1, e2)));
}

// W[K,N] fp32 -> Wt[N,K] split bf16, batched over layers via blockIdx.z
__global__ void transpose_split(const float* __restrict__ W, __nv_bfloat16* __restrict__ Th,
                                __nv_bfloat16* __restrict__ Tl, int K, int N) {
    __shared__ float tile[32][33];
    const size_t lw = (size_t)blockIdx.z * K * N;
    const float* Wl = W + lw;
    __nv_bfloat16* Thl = Th + lw;
    __nv_bfloat16* Tll = Tl + lw;
    int n0 = blockIdx.x * 32, k0 = blockIdx.y * 32;
    int tx = threadIdx.x, ty = threadIdx.y;
#pragma unroll
    for (int i = 0; i < 4; i++)
        tile[ty + i * 8][tx] = Wl[(size_t)(k0 + ty + i * 8) * N + n0 + tx];
    __syncthreads();
#pragma unroll
    for (int i = 0; i < 4; i++) {
        int n = n0 + ty + i * 8;
        float v = tile[tx][ty + i * 8];
        __nv_bfloat16 h = __float2bfloat16(v);
        Thl[(size_t)n * K + k0 + tx] = h;
        Tll[(size_t)n * K + k0 + tx] = __float2bfloat16(v - __bfloat162float(h));
    }
}

__global__ void zero_pool() {
    int i = blockIdx.x * blockDim.x + threadIdx.x;
    if (i < NG * D) g_pooled[i] = 0.f;
    if (i < NG) g_cnt[i] = 0.f;
}
__global__ void count_nodes(const int* __restrict__ batch, int N) {
    int n = blockIdx.x * blockDim.x + threadIdx.x;
    if (n < N) atomicAdd(&g_cnt[batch[n]], 1.0f);
}
__global__ void pool_div() {
    int i = blockIdx.x * blockDim.x + threadIdx.x;
    if (i >= NG * D4) return;
    float inv = 1.0f / fmaxf(g_cnt[i >> 7], 1.0f);
    float4 v = reinterpret_cast<float4*>(g_pooled)[i];
    v.x *= inv; v.y *= inv; v.z *= inv; v.w *= inv;
    reinterpret_cast<float4*>(g_pooled)[i] = v;
}

// ---------------- launch ----------------
extern "C" void kernel_launch(void* const* d_in, const int* in_sizes, int n_in,
                              void* d_out, int out_size) {
    const int*   x     = (const int*)d_in[0];
    const int*   ei    = (const int*)d_in[1];
    const int*   ea    = (const int*)d_in[2];
    const int*   batch = (const int*)d_in[3];
    const float* ae1   = (const float*)d_in[4];
    const float* ae2   = (const float*)d_in[5];
    const float* be1   = (const float*)d_in[6];
    const float* be2   = (const float*)d_in[7];
    const float* W1    = (const float*)d_in[8];
    const float* b1    = (const float*)d_in[9];
    const float* W2    = (const float*)d_in[10];
    const float* b2    = (const float*)d_in[11];
    const float* pW1   = (const float*)d_in[12];
    const float* pb1   = (const float*)d_in[13];
    const float* pW2   = (const float*)d_in[14];
    const float* pb2   = (const float*)d_in[15];

    const int N = in_sizes[3];
    const int E = in_sizes[1] / 2;

    cudaFuncSetAttribute(gemm_mma, cudaFuncAttributeMaxDynamicSharedMemorySize, GEMM_SMEM);

    void* p;
    cudaGetSymbolAddress(&p, g_h);      float* H = (float*)p;
    cudaGetSymbolAddress(&p, g_agg);    float* AGG = (float*)p;
    cudaGetSymbolAddress(&p, g_t);      float* T = (float*)p;
    cudaGetSymbolAddress(&p, g_pooled); float* POOL = (float*)p;
    cudaGetSymbolAddress(&p, g_w1h);    __nv_bfloat16* W1H = (__nv_bfloat16*)p;
    cudaGetSymbolAddress(&p, g_w1l);    __nv_bfloat16* W1L = (__nv_bfloat16*)p;
    cudaGetSymbolAddress(&p, g_w2h);    __nv_bfloat16* W2H = (__nv_bfloat16*)p;
    cudaGetSymbolAddress(&p, g_w2l);    __nv_bfloat16* W2L = (__nv_bfloat16*)p;
    cudaGetSymbolAddress(&p, g_q1h);    __nv_bfloat16* Q1H = (__nv_bfloat16*)p;
    cudaGetSymbolAddress(&p, g_q1l);    __nv_bfloat16* Q1L = (__nv_bfloat16*)p;
    cudaGetSymbolAddress(&p, g_q2h);    __nv_bfloat16* Q2H = (__nv_bfloat16*)p;
    cudaGetSymbolAddress(&p, g_q2l);    __nv_bfloat16* Q2L = (__nv_bfloat16*)p;
    float* OUT = (float*)d_out;

    const dim3 tb(32, 8);
    // batched weight prep
    transpose_split<<<dim3(1024 / 32, 512 / 32, NLAYER), tb>>>(W1, W1H, W1L, 512, 1024);
    transpose_split<<<dim3(512 / 32, 1024 / 32, NLAYER), tb>>>(W2, W2H, W2L, 1024, 512);
    transpose_split<<<dim3(16, 16, 1), tb>>>(pW1, Q1H, Q1L, 512, 512);
    transpose_split<<<dim3(16, 16, 1), tb>>>(pW2, Q2H, Q2L, 512, 512);

    const int gridND4 = (N * D4 + 255) / 256;
    const int mtiles = (N + 127) / 128;

    // pooling init (independent of h — do it early)
    zero_pool<<<(NG * D + 255) / 256, 256>>>();
    count_nodes<<<(N + 255) / 256, 256>>>(batch, N);

    // atom encode + fused layer-0 agg init
    atom_encode<<<gridND4, 256>>>(x, ae1, ae2, be1, be2, N);

    for (int l = 0; l < NLAYER; l++) {
        const float* be1l = be1 + (size_t)l * 8 * D;
        const float* be2l = be2 + (size_t)l * 4 * D;
        edge_scatter<<<(E + 1) / 2, 256>>>(ei, ei + E, ea, be1l, be2l, E);

        // hidden = relu(agg @ W1 + b1)  [N,1024] fp32
        gemm_mma<<<dim3(1024 / 128, mtiles), 256, GEMM_SMEM>>>(
            AGG, W1H + (size_t)l * 1024 * 512, W1L + (size_t)l * 1024 * 512,
            b1 + (size_t)l * 1024, T, N, 1024, 512, 1,
            nullptr, nullptr, nullptr, nullptr, nullptr);

        // h = hidden @ W2 + b2 (+relu unless last)  [N,512] fp32
        // fused: layers 0..3 also init next layer's agg; layer 4 also pools
        const bool last = (l == NLAYER - 1);
        float* aggOut = last ? nullptr : AGG;
        const float* se1 = last ? nullptr : (be1 + (size_t)(l + 1) * 8 * D + 6 * D);
        const float* se2 = last ? nullptr : (be2 + (size_t)(l + 1) * 4 * D + 3 * D);
        gemm_mma<<<dim3(512 / 128, mtiles), 256, GEMM_SMEM>>>(
            T, W2H + (size_t)l * 512 * 1024, W2L + (size_t)l * 512 * 1024,
            b2 + (size_t)l * 512, H, N, 512, 1024, last ? 0 : 1,
            aggOut, se1, se2,
            last ? POOL : nullptr, last ? batch : nullptr);
    }

    pool_div<<<(NG * D4 + 255) / 256, 256>>>();

    gemm_mma<<<dim3(4, NG / 128), 256, GEMM_SMEM>>>(
        POOL, Q1H, Q1L, pb1, T, NG, 512, 512, 1,
        nullptr, nullptr, nullptr, nullptr, nullptr);
    gemm_mma<<<dim3(4, NG / 128), 256, GEMM_SMEM>>>(
        T, Q2H, Q2L, pb2, OUT, NG, 512, 512, 0,
        nullptr, nullptr, nullptr, nullptr, nullptr);
}

// round 15
// speedup vs baseline: 1.0818x; 1.0818x over previous
#include <cuda_runtime.h>
#include <cuda_bf16.h>
#include <cstdint>
#include <cstddef>

// ---------------- problem constants ----------------
#define D      512
#define D4     128
#define MAXN   50000
#define MAXE   200000
#define NG     2048
#define NLAYER 5

// ---------------- scratch (device globals; no allocation allowed) ----------
__device__ float g_h[(size_t)MAXN * D];        // node features fp32
__device__ float g_agg[(size_t)MAXN * D];      // aggregated messages fp32
__device__ float g_t[(size_t)MAXN * 2 * D];    // MLP hidden fp32 [N,1024]
__device__ float g_pooled[(size_t)NG * D];
__device__ float g_cnt[NG];

// CSR (by destination), built once per launch
__device__ int g_cntE[MAXN];
__device__ int g_off[MAXN + 1];
__device__ int g_eidx[MAXE];

// split-bf16 transposed weights  Wt[n][k]
__device__ __nv_bfloat16 g_w1h[(size_t)NLAYER * 1024 * 512];
__device__ __nv_bfloat16 g_w1l[(size_t)NLAYER * 1024 * 512];
__device__ __nv_bfloat16 g_w2h[(size_t)NLAYER * 512 * 1024];
__device__ __nv_bfloat16 g_w2l[(size_t)NLAYER * 512 * 1024];
__device__ __nv_bfloat16 g_q1h[512 * 512];
__device__ __nv_bfloat16 g_q1l[512 * 512];
__device__ __nv_bfloat16 g_q2h[512 * 512];
__device__ __nv_bfloat16 g_q2l[512 * 512];

// ---------------- PTX helpers (baseline ISA only: sm_80+) ----------------
__device__ __forceinline__ uint32_t smem_u32(const void* p) {
    uint32_t a;
    asm("{ .reg .u64 t; cvta.to.shared.u64 t, %1; cvt.u32.u64 %0, t; }" : "=r"(a) : "l"(p));
    return a;
}

__device__ __forceinline__ void cp_async16(uint32_t dst, const void* src, bool pred) {
    int sz = pred ? 16 : 0;
    asm volatile("cp.async.cg.shared.global [%0], [%1], 16, %2;" :: "r"(dst), "l"(src), "r"(sz));
}

__device__ __forceinline__ void ldsm_x2(uint32_t* r, uint32_t addr) {
    asm volatile("ldmatrix.sync.aligned.m8n8.x2.shared.b16 {%0,%1}, [%2];"
                 : "=r"(r[0]), "=r"(r[1]) : "r"(addr));
}

__device__ __forceinline__ void mma16816(float* c, const uint32_t* a, const uint32_t* b) {
    asm volatile("mma.sync.aligned.m16n8k16.row.col.f32.bf16.bf16.f32 "
                 "{%0,%1,%2,%3}, {%4,%5,%6,%7}, {%8,%9}, {%0,%1,%2,%3};"
                 : "+f"(c[0]), "+f"(c[1]), "+f"(c[2]), "+f"(c[3])
                 : "r"(a[0]), "r"(a[1]), "r"(a[2]), "r"(a[3]), "r"(b[0]), "r"(b[1]));
}

// split a float2 into packed bf16x2 hi + residual lo
__device__ __forceinline__ void split2(float2 f, uint32_t& h, uint32_t& l) {
    __nv_bfloat162 hb = __floats2bfloat162_rn(f.x, f.y);
    float r0 = f.x - __bfloat162float(hb.x);
    float r1 = f.y - __bfloat162float(hb.y);
    __nv_bfloat162 lb = __floats2bfloat162_rn(r0, r1);
    h = *reinterpret_cast<uint32_t*>(&hb);
    l = *reinterpret_cast<uint32_t*>(&lb);
}

__device__ __forceinline__ void red_add_v2(float* addr, float a, float b) {
    asm volatile("red.global.add.v2.f32 [%0], {%1,%2};"
                 :: "l"(addr), "f"(a), "f"(b) : "memory");
}

// ---------------- smem layout (dynamic) ----------------
static constexpr int A_STRIDE_F = 24;
static constexpr int A_CHUNK    = 128 * A_STRIDE_F * 4;   // 12288 B
static constexpr int B_STRIDE_H = 40;
static constexpr int B_CHUNK    = 128 * B_STRIDE_H * 2;   // 10240 B
static constexpr int STAGE_SZ   = A_CHUNK + B_CHUNK;      // 22528 B
static constexpr int NSTAGE     = 3;
static constexpr int GEMM_SMEM  = NSTAGE * STAGE_SZ;      // 67584 B

// ---------------- split-bf16 warp-MMA GEMM, fp32 A (R13 config) -----------
// C[M,Ncols] = act(A[M,K] @ Wt[Ncols,K]^T + bias); Ncols%128==0, K%16==0.
// 8 warps as 2(row)x4(col); warp tile 64x32; 3-stage cp.async pipeline.
// Pool != null: also red.add v into Pool[batch[row]*Ncols + col]
__global__ __launch_bounds__(256)
void gemm_mma(const float* __restrict__ A,
              const __nv_bfloat16* __restrict__ Bhi, const __nv_bfloat16* __restrict__ Blo,
              const float* __restrict__ bias, float* __restrict__ Cf,
              int M, int Ncols, int K, int relu,
              float* __restrict__ Pool, const int* __restrict__ batch) {
    extern __shared__ char smem[];
    const int tid = threadIdx.x;
    const int lane = tid & 31;
    const int wid = tid >> 5;
    const int wm = wid & 1;          // 2 warp-rows  -> 64 rows each
    const int wn = wid >> 1;         // 4 warp-cols  -> 32 cols each
    const int r0 = blockIdx.y * 128;
    const int c0 = blockIdx.x * 128;

    float acc[4][4][4];
#pragma unroll
    for (int i = 0; i < 4; i++)
#pragma unroll
        for (int j = 0; j < 4; j++)
#pragma unroll
            for (int e = 0; e < 4; e++) acc[i][j][e] = 0.f;

    const int nk = K >> 4;

    auto load_stage = [&](int c, int s) {
        const int k0 = c << 4;
        char* st = smem + s * STAGE_SZ;
#pragma unroll
        for (int it = 0; it < 2; it++) {
            int id = tid + it * 256;
            int row = id >> 2, ch = id & 3;
            const float* src = A + (size_t)(r0 + row) * K + k0 + ch * 4;
            uint32_t dst = smem_u32(st + row * (A_STRIDE_F * 4) + ch * 16);
            cp_async16(dst, src, (r0 + row) < M);
        }
#pragma unroll
        for (int it = 0; it < 2; it++) {
            int id = tid + it * 256;
            int row = id >> 2, ch = id & 3;
            const __nv_bfloat16* src = (ch < 2 ? Bhi : Blo) + (size_t)(c0 + row) * K + k0 + (ch & 1) * 8;
            uint32_t dst = smem_u32(st + A_CHUNK + row * (B_STRIDE_H * 2) + ch * 16);
            cp_async16(dst, src, true);
        }
        asm volatile("cp.async.commit_group;" ::: "memory");
    };

    load_stage(0, 0);
    if (nk > 1) load_stage(1, 1);

    const int g = lane >> 2, tig = lane & 3;

    for (int c = 0; c < nk; c++) {
        const int s = c % NSTAGE;
        if (c + 2 < nk) {
            load_stage(c + 2, (c + 2) % NSTAGE);
            asm volatile("cp.async.wait_group 2;" ::: "memory");
        } else if (c + 1 < nk) {
            asm volatile("cp.async.wait_group 1;" ::: "memory");
        } else {
            asm volatile("cp.async.wait_group 0;" ::: "memory");
        }
        __syncthreads();

        const float* sA = reinterpret_cast<const float*>(smem + s * STAGE_SZ);
        char* sBbase = smem + s * STAGE_SZ + A_CHUNK;

        uint32_t ah[4][4], al[4][4];
#pragma unroll
        for (int mi = 0; mi < 4; mi++) {
            const int ra = wm * 64 + mi * 16 + g;
            float2 f0 = *reinterpret_cast<const float2*>(sA + ra * A_STRIDE_F + tig * 2);
            float2 f1 = *reinterpret_cast<const float2*>(sA + (ra + 8) * A_STRIDE_F + tig * 2);
            float2 f2 = *reinterpret_cast<const float2*>(sA + ra * A_STRIDE_F + tig * 2 + 8);
            float2 f3 = *reinterpret_cast<const float2*>(sA + (ra + 8) * A_STRIDE_F + tig * 2 + 8);
            split2(f0, ah[mi][0], al[mi][0]);
            split2(f1, ah[mi][1], al[mi][1]);
            split2(f2, ah[mi][2], al[mi][2]);
            split2(f3, ah[mi][3], al[mi][3]);
        }
        uint32_t bh[4][2], bl[4][2];
#pragma unroll
        for (int ni = 0; ni < 4; ni++) {
            uint32_t bd = smem_u32(sBbase + (wn * 32 + ni * 8 + (lane & 7)) * (B_STRIDE_H * 2)
                                   + ((lane >> 3) & 1) * 16);
            ldsm_x2(bh[ni], bd);
            ldsm_x2(bl[ni], bd + 32);
        }
#pragma unroll
        for (int mi = 0; mi < 4; mi++)
#pragma unroll
            for (int ni = 0; ni < 4; ni++) {
                mma16816(acc[mi][ni], ah[mi], bh[ni]);
                mma16816(acc[mi][ni], ah[mi], bl[ni]);
                mma16816(acc[mi][ni], al[mi], bh[ni]);
            }
        __syncthreads();
    }

    // ---- epilogue: bias + act + fp32 store (+ fused pool) ----
#pragma unroll
    for (int mi = 0; mi < 4; mi++) {
#pragma unroll
        for (int ni = 0; ni < 4; ni++) {
            const int col = c0 + wn * 32 + ni * 8 + tig * 2;
            const float b0 = __ldg(bias + col), b1 = __ldg(bias + col + 1);
#pragma unroll
            for (int h = 0; h < 2; h++) {
                const int row = r0 + wm * 64 + mi * 16 + g + h * 8;
                if (row < M) {
                    float v0 = acc[mi][ni][h * 2 + 0] + b0;
                    float v1 = acc[mi][ni][h * 2 + 1] + b1;
                    if (relu) { v0 = fmaxf(v0, 0.f); v1 = fmaxf(v1, 0.f); }
                    *reinterpret_cast<float2*>(Cf + (size_t)row * Ncols + col) = make_float2(v0, v1);
                    if (Pool) {
                        int gi = __ldg(batch + row);
                        red_add_v2(Pool + (size_t)gi * Ncols + col, v0, v1);
                    }
                }
            }
        }
    }
}

// ---------------- elementwise / graph kernels ----------------
__device__ __forceinline__ float4 f4add(float4 a, float4 b) {
    return make_float4(a.x + b.x, a.y + b.y, a.z + b.z, a.w + b.w);
}

__global__ void atom_encode(const int* __restrict__ x, const float* __restrict__ ae1,
                            const float* __restrict__ ae2, int N) {
    int i = blockIdx.x * blockDim.x + threadIdx.x;
    if (i >= N * D4) return;
    int n = i >> 7, c = i & (D4 - 1);
    float4 v1 = reinterpret_cast<const float4*>(ae1)[x[2 * n] * D4 + c];
    float4 v2 = reinterpret_cast<const float4*>(ae2)[x[2 * n + 1] * D4 + c];
    reinterpret_cast<float4*>(g_h)[i] = f4add(v1, v2);
}

// ---- CSR build (once per launch) ----
__global__ void zero_cnt(int N) {
    int i = blockIdx.x * blockDim.x + threadIdx.x;
    if (i < N) g_cntE[i] = 0;
}
__global__ void count_dst(const int* __restrict__ dst, int E) {
    int e = blockIdx.x * blockDim.x + threadIdx.x;
    if (e < E) atomicAdd(&g_cntE[dst[e]], 1);
}
// single-block exclusive scan: off[0..N], off[i+1] = sum cnt[0..i]
__global__ void scan_off(int N) {
    __shared__ int sm[1024];
    __shared__ int carry;
    int tid = threadIdx.x;
    if (tid == 0) carry = 0;
    __syncthreads();
    for (int base = 0; base < N; base += 1024) {
        int i = base + tid;
        int v = (i < N) ? g_cntE[i] : 0;
        sm[tid] = v;
        __syncthreads();
#pragma unroll
        for (int d = 1; d < 1024; d <<= 1) {
            int t = (tid >= d) ? sm[tid - d] : 0;
            __syncthreads();
            sm[tid] += t;
            __syncthreads();
        }
        if (i < N) g_off[i + 1] = carry + sm[tid];
        __syncthreads();
        if (tid == 0) carry += sm[1023];
        __syncthreads();
    }
    if (tid == 0) g_off[0] = 0;
}
__global__ void fill_eidx(const int* __restrict__ dst, int E) {
    int e = blockIdx.x * blockDim.x + threadIdx.x;
    if (e < E) {
        int d = dst[e];
        int pos = g_off[d] + atomicAdd(&g_cntE[d], 1);
        g_eidx[pos] = e;
    }
}

// agg[n] = h[n] + selfloop emb + sum_{e: dst=n} (h[src[e]] + e1 + e2)
// one 128-thread block per node; thread c owns float4 c. No atomics.
__global__ void gather_agg(const int* __restrict__ src, const int* __restrict__ ea,
                           const float* __restrict__ be1l, const float* __restrict__ be2l,
                           int N) {
    const int n = blockIdx.x;
    const int c = threadIdx.x;          // 0..127
    const float4* h4 = reinterpret_cast<const float4*>(g_h);
    const float4* e14 = reinterpret_cast<const float4*>(be1l);
    const float4* e24 = reinterpret_cast<const float4*>(be2l);

    float4 acc = f4add(h4[(size_t)n * D4 + c],
                       f4add(e14[6 * D4 + c], e24[3 * D4 + c]));

    const int j0 = __ldg(&g_off[n]);
    const int j1 = __ldg(&g_off[n + 1]);
    for (int j = j0; j < j1; j++) {
        int e = __ldg(&g_eidx[j]);
        int s = __ldg(&src[e]);
        int a0 = __ldg(&ea[2 * e]);
        int a1 = __ldg(&ea[2 * e + 1]);
        acc = f4add(acc, f4add(h4[(size_t)s * D4 + c],
                               f4add(e14[a0 * D4 + c], e24[a1 * D4 + c])));
    }
    reinterpret_cast<float4*>(g_agg)[(size_t)n * D4 + c] = acc;
}

// W[K,N] fp32 -> Wt[N,K] split bf16, batched over layers via blockIdx.z
__global__ void transpose_split(const float* __restrict__ W, __nv_bfloat16* __restrict__ Th,
                                __nv_bfloat16* __restrict__ Tl, int K, int N) {
    __shared__ float tile[32][33];
    const size_t lw = (size_t)blockIdx.z * K * N;
    const float* Wl = W + lw;
    __nv_bfloat16* Thl = Th + lw;
    __nv_bfloat16* Tll = Tl + lw;
    int n0 = blockIdx.x * 32, k0 = blockIdx.y * 32;
    int tx = threadIdx.x, ty = threadIdx.y;
#pragma unroll
    for (int i = 0; i < 4; i++)
        tile[ty + i * 8][tx] = Wl[(size_t)(k0 + ty + i * 8) * N + n0 + tx];
    __syncthreads();
#pragma unroll
    for (int i = 0; i < 4; i++) {
        int n = n0 + ty + i * 8;
        float v = tile[tx][ty + i * 8];
        __nv_bfloat16 h = __float2bfloat16(v);
        Thl[(size_t)n * K + k0 + tx] = h;
        Tll[(size_t)n * K + k0 + tx] = __float2bfloat16(v - __bfloat162float(h));
    }
}

__global__ void zero_pool() {
    int i = blockIdx.x * blockDim.x + threadIdx.x;
    if (i < NG * D) g_pooled[i] = 0.f;
    if (i < NG) g_cnt[i] = 0.f;
}
__global__ void count_nodes(const int* __restrict__ batch, int N) {
    int n = blockIdx.x * blockDim.x + threadIdx.x;
    if (n < N) atomicAdd(&g_cnt[batch[n]], 1.0f);
}
__global__ void pool_div() {
    int i = blockIdx.x * blockDim.x + threadIdx.x;
    if (i >= NG * D4) return;
    float inv = 1.0f / fmaxf(g_cnt[i >> 7], 1.0f);
    float4 v = reinterpret_cast<float4*>(g_pooled)[i];
    v.x *= inv; v.y *= inv; v.z *= inv; v.w *= inv;
    reinterpret_cast<float4*>(g_pooled)[i] = v;
}

// ---------------- launch ----------------
extern "C" void kernel_launch(void* const* d_in, const int* in_sizes, int n_in,
                              void* d_out, int out_size) {
    const int*   x     = (const int*)d_in[0];
    const int*   ei    = (const int*)d_in[1];
    const int*   ea    = (const int*)d_in[2];
    const int*   batch = (const int*)d_in[3];
    const float* ae1   = (const float*)d_in[4];
    const float* ae2   = (const float*)d_in[5];
    const float* be1   = (const float*)d_in[6];
    const float* be2   = (const float*)d_in[7];
    const float* W1    = (const float*)d_in[8];
    const float* b1    = (const float*)d_in[9];
    const float* W2    = (const float*)d_in[10];
    const float* b2    = (const float*)d_in[11];
    const float* pW1   = (const float*)d_in[12];
    const float* pb1   = (const float*)d_in[13];
    const float* pW2   = (const float*)d_in[14];
    const float* pb2   = (const float*)d_in[15];

    const int N = in_sizes[3];
    const int E = in_sizes[1] / 2;
    const int* src = ei;
    const int* dst = ei + E;

    cudaFuncSetAttribute(gemm_mma, cudaFuncAttributeMaxDynamicSharedMemorySize, GEMM_SMEM);

    void* p;
    cudaGetSymbolAddress(&p, g_h);      float* H = (float*)p;
    cudaGetSymbolAddress(&p, g_agg);    float* AGG = (float*)p;
    cudaGetSymbolAddress(&p, g_t);      float* T = (float*)p;
    cudaGetSymbolAddress(&p, g_pooled); float* POOL = (float*)p;
    cudaGetSymbolAddress(&p, g_w1h);    __nv_bfloat16* W1H = (__nv_bfloat16*)p;
    cudaGetSymbolAddress(&p, g_w1l);    __nv_bfloat16* W1L = (__nv_bfloat16*)p;
    cudaGetSymbolAddress(&p, g_w2h);    __nv_bfloat16* W2H = (__nv_bfloat16*)p;
    cudaGetSymbolAddress(&p, g_w2l);    __nv_bfloat16* W2L = (__nv_bfloat16*)p;
    cudaGetSymbolAddress(&p, g_q1h);    __nv_bfloat16* Q1H = (__nv_bfloat16*)p;
    cudaGetSymbolAddress(&p, g_q1l);    __nv_bfloat16* Q1L = (__nv_bfloat16*)p;
    cudaGetSymbolAddress(&p, g_q2h);    __nv_bfloat16* Q2H = (__nv_bfloat16*)p;
    cudaGetSymbolAddress(&p, g_q2l);    __nv_bfloat16* Q2L = (__nv_bfloat16*)p;
    float* OUT = (float*)d_out;

    const dim3 tb(32, 8);
    // batched weight prep
    transpose_split<<<dim3(1024 / 32, 512 / 32, NLAYER), tb>>>(W1, W1H, W1L, 512, 1024);
    transpose_split<<<dim3(512 / 32, 1024 / 32, NLAYER), tb>>>(W2, W2H, W2L, 1024, 512);
    transpose_split<<<dim3(16, 16, 1), tb>>>(pW1, Q1H, Q1L, 512, 512);
    transpose_split<<<dim3(16, 16, 1), tb>>>(pW2, Q2H, Q2L, 512, 512);

    // CSR build (once)
    zero_cnt<<<(N + 255) / 256, 256>>>(N);
    count_dst<<<(E + 255) / 256, 256>>>(dst, E);
    scan_off<<<1, 1024>>>(N);
    zero_cnt<<<(N + 255) / 256, 256>>>(N);
    fill_eidx<<<(E + 255) / 256, 256>>>(dst, E);

    // pooling init
    zero_pool<<<(NG * D + 255) / 256, 256>>>();
    count_nodes<<<(N + 255) / 256, 256>>>(batch, N);

    const int gridND4 = (N * D4 + 255) / 256;
    const int mtiles = (N + 127) / 128;

    atom_encode<<<gridND4, 256>>>(x, ae1, ae2, N);

    for (int l = 0; l < NLAYER; l++) {
        const float* be1l = be1 + (size_t)l * 8 * D;
        const float* be2l = be2 + (size_t)l * 4 * D;

        // agg = selfloop + gathered messages (no atomics)
        gather_agg<<<N, 128>>>(src, ea, be1l, be2l, N);

        // hidden = relu(agg @ W1 + b1)  [N,1024] fp32
        gemm_mma<<<dim3(1024 / 128, mtiles), 256, GEMM_SMEM>>>(
            AGG, W1H + (size_t)l * 1024 * 512, W1L + (size_t)l * 1024 * 512,
            b1 + (size_t)l * 1024, T, N, 1024, 512, 1,
            nullptr, nullptr);

        // h = hidden @ W2 + b2 (+relu unless last); last layer also pools
        const bool last = (l == NLAYER - 1);
        gemm_mma<<<dim3(512 / 128, mtiles), 256, GEMM_SMEM>>>(
            T, W2H + (size_t)l * 512 * 1024, W2L + (size_t)l * 512 * 1024,
            b2 + (size_t)l * 512, H, N, 512, 1024, last ? 0 : 1,
            last ? POOL : nullptr, last ? batch : nullptr);
    }

    pool_div<<<(NG * D4 + 255) / 256, 256>>>();

    gemm_mma<<<dim3(4, NG / 128), 256, GEMM_SMEM>>>(
        POOL, Q1H, Q1L, pb1, T, NG, 512, 512, 1, nullptr, nullptr);
    gemm_mma<<<dim3(4, NG / 128), 256, GEMM_SMEM>>>(
        T, Q2H, Q2L, pb2, OUT, NG, 512, 512, 0, nullptr, nullptr);
}